// round 7
// baseline (speedup 1.0000x reference)
#include <cuda_runtime.h>

// Problem constants (fixed by setup_inputs)
#define NB        64
#define SD        52
#define CELLS     (SD * SD)             // 2704
#define CH        255
#define NQUADS    (NB * CELLS / 4)      // 43264 (one warp per quad of 4 cells)
#define QPI       (CELLS / 4)           // 676 quads per image
#define EPSF      1e-6f
#define IOU_T     0.7f
#define SCALE_IDX 2

__global__ void zero_out_kernel(float* out) {
    int t = threadIdx.x;
    if (t < 257) out[t] = 0.0f;
}

__device__ __forceinline__ float bfly_sum(float v) {
    #pragma unroll
    for (int o = 16; o > 0; o >>= 1) v += __shfl_xor_sync(0xffffffffu, v, o);
    return v;
}

// select among 3 values by runtime index (avoids register-array indexing)
#define SEL3(i, a, b, c) ((i) == 0 ? (a) : ((i) == 1 ? (b) : (c)))

__global__ __launch_bounds__(128, 6) void yolo_loss_kernel(
    const float* __restrict__ yhat,
    const float* __restrict__ ytru,
    const float* __restrict__ anchors,
    float* __restrict__ out)
{
    const int wl   = threadIdx.x >> 5;
    const int lane = threadIdx.x & 31;
    const int quad = blockIdx.x * 4 + wl;      // 0..43263 (grid exact)
    const int n    = quad / QPI;
    const int cell0 = (quad % QPI) * 4;
    const int gi   = cell0 / SD;               // 52%4==0 -> row fixed within quad
    const int gj0  = cell0 % SD;               // gj0+3 <= 51, never wraps

    const float invS = 1.0f / (float)SD;
    const float fi = (float)gi;

    float aw[3], ah[3];
    #pragma unroll
    for (int b = 0; b < 3; b++) {
        aw[b] = __ldg(anchors + SCALE_IDX * 6 + 2 * b);
        ah[b] = __ldg(anchors + SCALE_IDX * 6 + 2 * b + 1);
    }

    float accC = 0.0f, accK = 0.0f, accN = 0.0f, accO = 0.0f;

    const float* HQ = yhat + (size_t)(n * CELLS + cell0) * CH;
    const float* YQ = ytru + (size_t)(n * CELLS + cell0) * CH;

    #pragma unroll
    for (int g = 0; g < 4; g++) {
        const float* Hb = HQ + g * CH;
        const float* Yb = YQ + g * CH;
        const float fj = (float)(gj0 + g);

        // ---- Load 6 records (H0,H1,H2,Y0,Y1,Y2), 85 floats each, 32-lane
        // coalesced: 3 scalar LDGs per record, each <=2 cache lines.
        float p0[6], p1[6], p2[6];
        #pragma unroll
        for (int r = 0; r < 6; r++) {
            const float* base = (r < 3) ? (Hb + r * 85) : (Yb + (r - 3) * 85);
            p0[r] = __ldg(base + lane);
            p1[r] = __ldg(base + 32 + lane);
            p2[r] = (lane < 21) ? __ldg(base + 64 + lane) : 0.0f;
        }

        // ---- Broadcast the 5 box fields of each record to all lanes.
        float cx[6], cy[6], bw[6], bh[6], cf[6];
        #pragma unroll
        for (int r = 0; r < 6; r++) {
            float xr = __shfl_sync(0xffffffffu, p0[r], 0);
            float yr = __shfl_sync(0xffffffffu, p0[r], 1);
            bw[r]    = __shfl_sync(0xffffffffu, p0[r], 2);
            bh[r]    = __shfl_sync(0xffffffffu, p0[r], 3);
            cf[r]    = __shfl_sync(0xffffffffu, p0[r], 4);
            cx[r] = (xr + fj) * invS;
            cy[r] = (yr + fi) * invS;
        }

        // ---- IOU 3x3 (register-only, warp-uniform):
        // per-pb max -> noobj; per-tb argmax (first max) -> responsible box.
        int   idx_t[3];
        float best[3] = {-1.0f, -1.0f, -1.0f};
        float noobjv = 0.0f;
        #pragma unroll
        for (int pb = 0; pb < 3; pb++) {
            float px1 = cx[pb] - 0.5f * bw[pb], px2 = cx[pb] + 0.5f * bw[pb];
            float py1 = cy[pb] - 0.5f * bh[pb], py2 = cy[pb] + 0.5f * bh[pb];
            float pa  = bw[pb] * bh[pb];
            float m = -1.0f;
            #pragma unroll
            for (int tb = 0; tb < 3; tb++) {
                int r = 3 + tb;
                float wi = fmaxf(fminf(px2, cx[r] + 0.5f * bw[r]) -
                                 fmaxf(px1, cx[r] - 0.5f * bw[r]), 0.0f);
                float hi = fmaxf(fminf(py2, cy[r] + 0.5f * bh[r]) -
                                 fmaxf(py1, cy[r] - 0.5f * bh[r]), 0.0f);
                float inter = wi * hi;
                float iou = inter / (pa + bw[r] * bh[r] - inter + EPSF);
                m = fmaxf(m, iou);
                if (iou > best[tb]) { best[tb] = iou; idx_t[tb] = pb; }
            }
            if (m < IOU_T) noobjv += cf[pb] * cf[pb];   // NO_OBJ_V3 target=0
        }
        accN += noobjv;

        // ---- Per-true-box losses. pb is runtime -> 2-deep selects.
        #pragma unroll
        for (int tb = 0; tb < 3; tb++) {
            const int pb = idx_t[tb];
            const int r  = 3 + tb;
            float ho = (cf[r] > 0.0f) ? 1.0f : 0.0f;

            float cxp = SEL3(pb, cx[0], cx[1], cx[2]);
            float cyp = SEL3(pb, cy[0], cy[1], cy[2]);
            float bwp = SEL3(pb, bw[0], bw[1], bw[2]);
            float bhp = SEL3(pb, bh[0], bh[1], bh[2]);
            float cfp = SEL3(pb, cf[0], cf[1], cf[2]);
            float awp = SEL3(pb, aw[0], aw[1], aw[2]);
            float ahp = SEL3(pb, ah[0], ah[1], ah[2]);

            float dx = (cxp - cx[r]) * (float)SD;       // == x_hat - x_true
            float dy = (cyp - cy[r]) * (float)SD;
            float dlw = __logf(bwp / awp + EPSF) - __logf(bw[r] / aw[tb] + EPSF);
            float dlh = __logf(bhp / ahp + EPSF) - __logf(bh[r] / ah[tb] + EPSF);
            float c = dx * dx + dy * dy + dlw * dlw + dlh * dlh;
            accC += c * ho * (2.0f - bw[r] * bh[r]);    // SCALE_COORD
            float dc = cfp - cf[r];
            accO += dc * dc * ho;

            // Class loss: same-lane pairing, select H parts by pb.
            float h0 = SEL3(pb, p0[0], p0[1], p0[2]);
            float h1 = SEL3(pb, p1[0], p1[1], p1[2]);
            float h2 = SEL3(pb, p2[0], p2[1], p2[2]);
            float d0 = h0 - p0[r];
            float d1 = h1 - p1[r];
            float d2 = h2 - p2[r];                      // lanes>=21: 0-0=0
            float s = d1 * d1 + d2 * d2;
            if (lane >= 5) s += d0 * d0;                // offsets 0-4 are fields
            accK += s * ho;
        }
    }

    // accC/accN/accO are warp-uniform; accK needs the lane reduction.
    accK = bfly_sum(accK);
    if (lane == 0) {
        // layout: coord[0:64) class[64:128) noobj[128:192) obj[192:256) prior[256]
        atomicAdd(out + 0 * NB + n, accC);
        atomicAdd(out + 1 * NB + n, accK);
        atomicAdd(out + 2 * NB + n, accN);
        atomicAdd(out + 3 * NB + n, accO);
    }
}

extern "C" void kernel_launch(void* const* d_in, const int* in_sizes, int n_in,
                              void* d_out, int out_size) {
    const float* yhat    = (const float*)d_in[0];
    const float* y       = (const float*)d_in[1];
    const float* anchors = (const float*)d_in[2];
    float* out = (float*)d_out;

    zero_out_kernel<<<1, 288>>>(out);
    yolo_loss_kernel<<<NQUADS / 4, 128>>>(yhat, y, anchors, out);  // 10816 blocks
}

// round 8
// speedup vs baseline: 1.4744x; 1.4744x over previous
#include <cuda_runtime.h>

// Problem constants (fixed by setup_inputs)
#define NB        64
#define SD        52
#define CELLS     (SD * SD)             // 2704
#define CH        255
#define QCELLS    4                     // cells per warp
#define NQUADS    (NB * CELLS / QCELLS) // 43264
#define QPI       (CELLS / QCELLS)      // 676 quads per image
#define EPSF      1e-6f
#define IOU_T     0.7f
#define SCALE_IDX 2

__global__ void zero_out_kernel(float* out) {
    int t = threadIdx.x;
    if (t < 257) out[t] = 0.0f;
}

__device__ __forceinline__ float warp_sum(float v) {
    #pragma unroll
    for (int o = 16; o > 0; o >>= 1) v += __shfl_down_sync(0xffffffffu, v, o);
    return v;
}

__global__ __launch_bounds__(128, 8) void yolo_loss_kernel(
    const float* __restrict__ yhat,
    const float* __restrict__ ytru,
    const float* __restrict__ anchors,
    float* __restrict__ out)
{
    const int wl   = threadIdx.x >> 5;
    const int lane = threadIdx.x & 31;
    const int quad = blockIdx.x * 4 + wl;     // 0..43263 (grid exact)
    const int n    = quad / QPI;              // image
    const int c0   = (quad % QPI) * QCELLS;

    const int g   = lane >> 3;                // cell within quad (0..3)
    const int sub = lane & 7;                 // lane within cell group
    const int cellIdx = c0 + g;
    const int gi = cellIdx / SD;
    const int gj = cellIdx % SD;

    const float* HQ = yhat + (size_t)(n * CELLS + c0) * CH;
    const float* YQ = ytru + (size_t)(n * CELLS + c0) * CH;
    const float* Hb = HQ + g * CH;
    const float* Yb = YQ + g * CH;

    // ---- Box fields: broadcast LDGs per 8-lane group (as in best kernel).
    const float invS = 1.0f / (float)SD;
    const float fj = (float)gj, fi = (float)gi;

    float hcx[3], hcy[3], hw[3], hh[3], hcf[3];
    float ycx[3], ycy[3], yw[3], yh[3], ycf[3];
    #pragma unroll
    for (int b = 0; b < 3; b++) {
        const float* hb = Hb + b * 85;
        const float* yb = Yb + b * 85;
        hcx[b] = (__ldg(hb + 0) + fj) * invS;
        hcy[b] = (__ldg(hb + 1) + fi) * invS;
        hw[b]  =  __ldg(hb + 2);
        hh[b]  =  __ldg(hb + 3);
        hcf[b] =  __ldg(hb + 4);
        ycx[b] = (__ldg(yb + 0) + fj) * invS;
        ycy[b] = (__ldg(yb + 1) + fi) * invS;
        yw[b]  =  __ldg(yb + 2);
        yh[b]  =  __ldg(yb + 3);
        ycf[b] =  __ldg(yb + 4);
    }

    // ---- IOU 3x3: per-pb max -> noobj term; per-tb argmax -> responsible box.
    int   idx_t[3];
    float best_t[3] = {-1.0f, -1.0f, -1.0f};
    float noobj_acc = 0.0f;
    #pragma unroll
    for (int pb = 0; pb < 3; pb++) {
        float px1 = hcx[pb] - 0.5f * hw[pb], px2 = hcx[pb] + 0.5f * hw[pb];
        float py1 = hcy[pb] - 0.5f * hh[pb], py2 = hcy[pb] + 0.5f * hh[pb];
        float pa  = hw[pb] * hh[pb];
        float m = -1.0f;
        #pragma unroll
        for (int tb = 0; tb < 3; tb++) {
            float wi = fmaxf(fminf(px2, ycx[tb] + 0.5f * yw[tb]) -
                             fmaxf(px1, ycx[tb] - 0.5f * yw[tb]), 0.0f);
            float hi = fmaxf(fminf(py2, ycy[tb] + 0.5f * yh[tb]) -
                             fmaxf(py1, ycy[tb] - 0.5f * yh[tb]), 0.0f);
            float inter = wi * hi;
            float uni = pa + yw[tb] * yh[tb] - inter;
            float iou = inter / (uni + EPSF);
            m = fmaxf(m, iou);
            if (iou > best_t[tb]) { best_t[tb] = iou; idx_t[tb] = pb; }
        }
        if (sub == 0 && m < IOU_T) noobj_acc += hcf[pb] * hcf[pb];  // NO_OBJ_V3
    }

    // ---- Scalar losses (one lane per cell).
    float coord_acc = 0.0f, obj_acc = 0.0f;
    if (sub == 0) {
        const float* anc = anchors + SCALE_IDX * 6;
        #pragma unroll
        for (int tb = 0; tb < 3; tb++) {
            int pb = idx_t[tb];
            float ho = (ycf[tb] > 0.0f) ? 1.0f : 0.0f;
            float aw_p = __ldg(anc + pb * 2), ah_p = __ldg(anc + pb * 2 + 1);
            float aw_t = __ldg(anc + tb * 2), ah_t = __ldg(anc + tb * 2 + 1);
            float dx = (hcx[pb] - ycx[tb]) * (float)SD;   // == x_hat - x_true
            float dy = (hcy[pb] - ycy[tb]) * (float)SD;
            float dlw = __logf(hw[pb] / aw_p + EPSF) - __logf(yw[tb] / aw_t + EPSF);
            float dlh = __logf(hh[pb] / ah_p + EPSF) - __logf(yh[tb] / ah_t + EPSF);
            float c = dx * dx + dy * dy + dlw * dlw + dlh * dlh;
            coord_acc += c * ho * (2.0f - yw[tb] * yh[tb]);   // SCALE_COORD
            float dc = hcf[pb] - ycf[tb];
            obj_acc += dc * dc * ho;
        }
    }

    // ---- Pack per-cell metadata: idx_t (2b x3) + have_obj (1b x3).
    unsigned meta = (unsigned)idx_t[0] | ((unsigned)idx_t[1] << 2) |
                    ((unsigned)idx_t[2] << 4) |
                    ((ycf[0] > 0.0f ? 1u : 0u) << 6) |
                    ((ycf[1] > 0.0f ? 1u : 0u) << 7) |
                    ((ycf[2] > 0.0f ? 1u : 0u) << 8);

    // ---- Class loss: serialize cells, all 32 lanes load 128B-contiguous
    // windows (nL~2 per LDG instead of 4). Branches are warp-uniform.
    float cls_acc = 0.0f;
    #pragma unroll
    for (int i = 0; i < QCELLS; i++) {
        unsigned m = __shfl_sync(0xffffffffu, meta, i * 8);
        const float* Hc0 = HQ + i * CH;
        const float* Yc0 = YQ + i * CH;
        #pragma unroll
        for (int tb = 0; tb < 3; tb++) {
            if (m & (64u << tb)) {
                int pb = (m >> (2 * tb)) & 3;
                const float* h = Hc0 + pb * 85 + 5;
                const float* y = Yc0 + tb * 85 + 5;
                float d0 = __ldg(h + lane)      - __ldg(y + lane);
                float d1 = __ldg(h + lane + 32) - __ldg(y + lane + 32);
                float s = d0 * d0 + d1 * d1;
                if (lane < 16) {
                    float d2 = __ldg(h + lane + 64) - __ldg(y + lane + 64);
                    s += d2 * d2;
                }
                cls_acc += s;
            }
        }
    }

    // ---- Warp reduction (all 4 cells share image n) + atomics.
    coord_acc = warp_sum(coord_acc);
    cls_acc   = warp_sum(cls_acc);
    noobj_acc = warp_sum(noobj_acc);
    obj_acc   = warp_sum(obj_acc);

    if (lane == 0) {
        // layout: coord[0:64) class[64:128) noobj[128:192) obj[192:256) prior[256]
        atomicAdd(out + 0 * NB + n, coord_acc);
        atomicAdd(out + 1 * NB + n, cls_acc);
        atomicAdd(out + 2 * NB + n, noobj_acc);
        atomicAdd(out + 3 * NB + n, obj_acc);
    }
}

extern "C" void kernel_launch(void* const* d_in, const int* in_sizes, int n_in,
                              void* d_out, int out_size) {
    const float* yhat    = (const float*)d_in[0];
    const float* y       = (const float*)d_in[1];
    const float* anchors = (const float*)d_in[2];
    float* out = (float*)d_out;

    zero_out_kernel<<<1, 288>>>(out);
    yolo_loss_kernel<<<NQUADS / 4, 128>>>(yhat, y, anchors, out);  // 10816 blocks
}